// round 8
// baseline (speedup 1.0000x reference)
#include <cuda_runtime.h>
#include <cuda_bf16.h>

// SSM kernel: out[l*256 + i] = exp(l * A[i][i]) * B[i] * C[i] + D
// L = 262144, n = 256. Pure write-bandwidth problem:
//   val_{l+4} = val_l * r4 + c,   r4 = exp(4a),  c = d*(1-r4)
// Steady-state inner loop: 1 FFMA per channel + 1 STG.128 per 4 channels.
//
// Prologue is cooperative: per block only 2 expf per CHANNEL are needed
// (r1 = exp(a), estart = exp(l_base*a)); one thread per channel computes
// them into smem, consumers derive r4 = r1^4 and v_s = estart*r1^s*bc + d
// with cheap FMULs. This cuts MUFU work 4x vs computing 8 expf per thread.

#define NCH 256          // SSM_DIM
#define RPB 128          // rows (l values) per block -> grid = 2048
#define THREADS 256      // 64 float4-lanes * 4 sub-rows

__global__ __launch_bounds__(THREADS)
void ssm_kernel(const float* __restrict__ A,
                const float* __restrict__ B,
                const float* __restrict__ C,
                const float* __restrict__ D,
                float* __restrict__ out,
                int L)
{
    __shared__ __align__(16) float sm_r1[NCH];  // exp(a_ch)
    __shared__ __align__(16) float sm_es[NCH];  // exp(l_base * a_ch)
    __shared__ __align__(16) float sm_bc[NCH];  // B_ch * C_ch

    const int t     = threadIdx.x;
    const int lbase = blockIdx.x * RPB;

    // ---- cooperative prologue: one channel per thread, 2 expf each ----
    {
        const float a = A[t * 257];             // diag of A, stride 257
        sm_r1[t] = expf(a);
        sm_es[t] = expf((float)lbase * a);      // lbase <= 2^18 exact in fp32
        sm_bc[t] = B[t] * C[t];
    }
    __syncthreads();

    const int j  = t & 63;    // float4 lane: channels 4j..4j+3
    const int s  = t >> 6;    // sub-row 0..3
    const int l0 = lbase + s;
    if (l0 >= L) return;

    const float d = D[0];

    const float4 r1v = reinterpret_cast<const float4*>(sm_r1)[j];
    const float4 esv = reinterpret_cast<const float4*>(sm_es)[j];
    const float4 bcv = reinterpret_cast<const float4*>(sm_bc)[j];

    // r1^s via 2-bit exponent (s in 0..3), r4 = r1^4, c = d*(1-r4).
    const bool b1 = (s & 1), b2 = (s & 2);

    const float r1_0 = r1v.x, r1_1 = r1v.y, r1_2 = r1v.z, r1_3 = r1v.w;
    const float q0 = r1_0 * r1_0, q1 = r1_1 * r1_1,
                q2 = r1_2 * r1_2, q3 = r1_3 * r1_3;

    const float r40 = q0 * q0, r41 = q1 * q1, r42 = q2 * q2, r43 = q3 * q3;

    float p0 = b1 ? r1_0 : 1.0f;  if (b2) p0 *= q0;
    float p1 = b1 ? r1_1 : 1.0f;  if (b2) p1 *= q1;
    float p2 = b1 ? r1_2 : 1.0f;  if (b2) p2 *= q2;
    float p3 = b1 ? r1_3 : 1.0f;  if (b2) p3 *= q3;

    float v0 = fmaf(esv.x * p0, bcv.x, d);   // exp(l0*a)*bc + d
    float v1 = fmaf(esv.y * p1, bcv.y, d);
    float v2 = fmaf(esv.z * p2, bcv.z, d);
    float v3 = fmaf(esv.w * p3, bcv.w, d);

    const float c0 = fmaf(-r40, d, d);       // d*(1-r4)
    const float c1 = fmaf(-r41, d, d);
    const float c2 = fmaf(-r42, d, d);
    const float c3 = fmaf(-r43, d, d);

    // float4 index: (l*256 + 4j)/4 = l*64 + j.
    float4* o = reinterpret_cast<float4*>(out) + (size_t)l0 * 64 + j;

    const int rows_left = L - l0;
    const int iters = (rows_left + 3) >> 2;
    const int full  = (iters < RPB / 4) ? iters : RPB / 4;   // 32

#pragma unroll 8
    for (int it = 0; it < full; ++it) {
        float4 val;
        val.x = v0;
        val.y = v1;
        val.z = v2;
        val.w = v3;
        __stcs(o, val);            // streaming store; output never re-read
        v0 = fmaf(v0, r40, c0);    // val' = val*r4 + d*(1-r4)
        v1 = fmaf(v1, r41, c1);
        v2 = fmaf(v2, r42, c2);
        v3 = fmaf(v3, r43, c3);
        o += 4 * 64;               // advance 4 rows
    }
}

extern "C" void kernel_launch(void* const* d_in, const int* in_sizes, int n_in,
                              void* d_out, int out_size)
{
    // Input order per metadata: [L (int32 scalar)], A(256x256), B(256), C(256), D(1).
    const int base = (n_in >= 5) ? 1 : 0;
    const float* A = (const float*)d_in[base + 0];
    const float* B = (const float*)d_in[base + 1];
    const float* C = (const float*)d_in[base + 2];
    const float* D = (const float*)d_in[base + 3];
    float* out = (float*)d_out;

    const int L = out_size / NCH;                 // out is (L, 256) fp32
    const int grid = (L + RPB - 1) / RPB;         // 2048 for L = 262144

    ssm_kernel<<<grid, THREADS>>>(A, B, C, D, out, L);
}